// round 10
// baseline (speedup 1.0000x reference)
#include <cuda_runtime.h>

// ISTSimulator: B=65536, V=2, L=200 per-lane recurrence.
// Round 10: D/F recurrence split across thread halves -> 2x resident warps
// (8192 total, ~55/SM) to kill latency exposure. D-threads: u' = u - lam*u^beta
// (2 MUFU/step). F-threads: geometric sigmoid w/ 8-step exact reseed + R9
// warp-uniform hazard votes (~1.125 MUFU/step). Flush adds kd*D + kf*F terms.
// 16-step smem chunks, conflict-free stride-17 staging, coalesced float4 out.

#define LOG2E_F 1.4426950408889634f
#define BT 128                         // threads per block
#define LPB 64                         // lanes per block (half of BT)
#define SR 17                          // smem row stride (16 steps + 1 pad)

__device__ __forceinline__ float ex2a(float x) {
    float r; asm("ex2.approx.ftz.f32 %0, %1;" : "=f"(r) : "f"(x)); return r;
}
__device__ __forceinline__ float lg2a(float x) {
    float r; asm("lg2.approx.f32 %0, %1;" : "=f"(r) : "f"(x)); return r;
}
__device__ __forceinline__ float rcpa(float x) {
    float r; asm("rcp.approx.ftz.f32 %0, %1;" : "=f"(r) : "f"(x)); return r;
}

__global__ void __launch_bounds__(BT, 12) ist_split_kernel(
    const float* __restrict__ in, float* __restrict__ out)
{
    __shared__ float smd[LPB * SR];    // kd * D terms
    __shared__ float smf[LPB * SR];    // kf * F terms
    int t  = threadIdx.x;
    int li = t & (LPB - 1);            // lane within block
    bool isD = t < LPB;                // warps 0-1: D, warps 2-3: F
    int base_lane = blockIdx.x * LPB;
    const float* p = in + (size_t)(base_lane + li) * 7;

    // ---- per-role state (union; dead half costs a few regs) ----
    float u = 1.0f;                    // D: u = 1 - D, stays in (0.3, 1]
    float F = 1e-12f;                  // F state
    float nlam = 0.f, beta = 0.f, kd = 0.f, nkd = 0.f;
    float mu = 0.f, kf = 0.f, na = 0.f, z0 = 0.f, c = 0.f;
    bool warp_geo = false;

    if (isD) {
        float lam = 0.001f * fmaxf(p[0], 0.0f);
        nlam = -lam;
        beta = fmaf(10.0f, fmaxf(p[1], 0.0f), 1.0f);
        kd   = p[2];
        nkd  = -kd;
    } else {
        mu = p[3];
        kf = p[4];
        float a = LOG2E_F / p[6];      // sigmoid: g = 1/(1 + 2^((nc-n)*a))
        z0 = p[5] * a;
        na = -a;
        c  = ex2a(na);                 // geometric ratio 2^{-a}
        // geometric path only if c is normal/finite/nonzero for all lanes
        warp_geo = __all_sync(0xffffffffu, fabsf(a) < 126.0f);
    }

    float* spd = &smd[li * SR];
    float* spf = &smf[li * SR];

    #pragma unroll 1
    for (int chunk = 0; chunk < 13; ++chunk) {
        int n0 = chunk * 16;
        int nsteps = (chunk < 12) ? 16 : 8;        // 200 = 12*16 + 8

        if (isD) {
            #pragma unroll 8
            for (int j = 0; j < nsteps; ++j) {
                float l  = lg2a(u);
                float pw = ex2a(beta * l);         // u^beta
                u = fmaf(nlam, pw, u);
                spd[j] = fmaf(nkd, u, kd);         // kd * D = kd*(1-u)
            }
        } else {
            #pragma unroll 1
            for (int g8 = 0; g8 < nsteps; g8 += 8) {
                float zs = fmaf((float)(n0 + g8), na, z0);   // exact group z
                float ze = fmaf(8.0f, na, zs);
                // pinned-at-reseed + crossing hazard (z monotone -> exact)
                bool pin_cross = (zs >  126.0f && ze <  26.0f) ||
                                 (zs < -126.0f && ze > -26.0f);
                bool cheap = warp_geo && !__any_sync(0xffffffffu, pin_cross);
                if (cheap) {
                    float e = ex2a(zs);                      // exact reseed
                    #pragma unroll
                    for (int jj = 0; jj < 8; ++jj) {
                        float g = rcpa(1.0f + e);
                        e *= c;
                        float q = fmaf(mu, F, 1e-12f);
                        F = fminf(fmaxf(fmaf(g, q, F), 0.0f), 1.0f);
                        spf[g8 + jj] = kf * F;
                    }
                } else {
                    #pragma unroll
                    for (int jj = 0; jj < 8; ++jj) {
                        float z = fmaf((float)jj, na, zs);   // literal jj
                        float e = ex2a(z);                   // saturates safely
                        float g = rcpa(1.0f + e);
                        float q = fmaf(mu, F, 1e-12f);
                        F = fminf(fmaxf(fmaf(g, q, F), 0.0f), 1.0f);
                        spf[g8 + jj] = kf * F;
                    }
                }
            }
        }
        __syncthreads();
        // flush: combine kd*D + kf*F, coalesced float4 stores
        if (nsteps == 16) {
            #pragma unroll
            for (int it = 0; it < 2; ++it) {
                int q4 = it * BT + t;              // 0..255
                int w  = q4 * 4;
                int r  = w >> 4;                   // lane row 0..63
                int cc = w & 15;                   // step col 0,4,8,12
                int sb = r * SR + cc;
                float4 v;
                v.x = smd[sb]     + smf[sb];
                v.y = smd[sb + 1] + smf[sb + 1];
                v.z = smd[sb + 2] + smf[sb + 2];
                v.w = smd[sb + 3] + smf[sb + 3];
                *reinterpret_cast<float4*>(
                    &out[(size_t)(base_lane + r) * 200 + n0 + cc]) = v;
            }
        } else {
            int w  = t * 4;                        // 512 words, 1 float4/thread
            int r  = w >> 3;                       // lane row 0..63
            int cc = w & 7;                        // step col 0,4
            int sb = r * SR + cc;
            float4 v;
            v.x = smd[sb]     + smf[sb];
            v.y = smd[sb + 1] + smf[sb + 1];
            v.z = smd[sb + 2] + smf[sb + 2];
            v.w = smd[sb + 3] + smf[sb + 3];
            *reinterpret_cast<float4*>(
                &out[(size_t)(base_lane + r) * 200 + n0 + cc]) = v;
        }
        __syncthreads();
    }
}

// generic fallback for unexpected shapes
__global__ void __launch_bounds__(256) ist_generic(
    const float* __restrict__ in, float* __restrict__ out, int n_lanes)
{
    int tid = blockIdx.x * blockDim.x + threadIdx.x;
    if (tid >= n_lanes) return;
    const float* p = in + (size_t)tid * 7;
    float lam  = 0.001f * fmaxf(p[0], 0.0f);
    float beta = fmaf(10.0f, fmaxf(p[1], 0.0f), 1.0f);
    float kd = p[2], mu = p[3], kf = p[4];
    float a = LOG2E_F / p[6], z0 = p[5] * a;
    float u = 1.0f, F = 1e-12f, nf = 0.0f;
    float* o = out + (size_t)tid * 200;
    for (int n = 0; n < 200; ++n) {
        float l  = lg2a(fmaxf(u, 1e-12f));
        float pw = ex2a(beta * l);
        u = fminf(fmaxf(fmaf(-lam, pw, u), 0.0f), 1.0f);
        float z = fmaf(-nf, a, z0);
        float g = rcpa(1.0f + ex2a(z));
        float q = fmaf(mu, F, 1e-12f);
        F = fminf(fmaxf(fmaf(g, q, F), 0.0f), 1.0f);
        o[n] = fmaf(kf, F, fmaf(-kd, u, kd));
        nf += 1.0f;
    }
}

extern "C" void kernel_launch(void* const* d_in, const int* in_sizes, int n_in,
                              void* d_out, int out_size)
{
    const float* in = (const float*)d_in[0];
    float* out = (float*)d_out;
    int n_lanes = in_sizes[0] / 7;
    if (n_lanes % LPB == 0) {
        ist_split_kernel<<<n_lanes / LPB, BT>>>(in, out);
    } else {
        ist_generic<<<(n_lanes + 255) / 256, 256>>>(in, out, n_lanes);
    }
}

// round 11
// speedup vs baseline: 1.0730x; 1.0730x over previous
#include <cuda_runtime.h>

// ISTSimulator: B=65536, V=2, L=200 per-lane recurrence.
// Round 11: D/F split (2x warps vs one-thread-per-lane) with R8's 32-step
// chunk geometry to eliminate R10's barrier/flush overhead.
//   D-warps (0-1): u' = u - lam*u^beta          (2 MUFU/step)
//   F-warps (2-3): geometric sigmoid, 8-step exact reseed + warp votes
// Flush combines kd*D + kf*F from two stride-33 arrays; conflict-free LDS,
// fully-coalesced STG.128.

#define LOG2E_F 1.4426950408889634f
#define BT 128                         // threads per block
#define LPB 64                         // lanes per block
#define SR 33                          // smem row stride (odd -> conflict-free)

__device__ __forceinline__ float ex2a(float x) {
    float r; asm("ex2.approx.ftz.f32 %0, %1;" : "=f"(r) : "f"(x)); return r;
}
__device__ __forceinline__ float lg2a(float x) {
    float r; asm("lg2.approx.f32 %0, %1;" : "=f"(r) : "f"(x)); return r;
}
__device__ __forceinline__ float rcpa(float x) {
    float r; asm("rcp.approx.ftz.f32 %0, %1;" : "=f"(r) : "f"(x)); return r;
}

__global__ void __launch_bounds__(BT, 12) ist_split_kernel(
    const float* __restrict__ in, float* __restrict__ out)
{
    __shared__ float smd[LPB * SR];    // kd * D terms
    __shared__ float smf[LPB * SR];    // kf * F terms
    int t  = threadIdx.x;
    int li = t & (LPB - 1);
    bool isD = t < LPB;                // warps 0-1: D, warps 2-3: F
    int base_lane = blockIdx.x * LPB;
    const float* p = in + (size_t)(base_lane + li) * 7;

    float u = 1.0f;                    // D: u = 1 - D, stays in (0.3, 1]
    float F = 1e-12f;
    float nlam = 0.f, beta = 0.f, kd = 0.f, nkd = 0.f;
    float mu = 0.f, kf = 0.f, na = 0.f, z0 = 0.f, c = 0.f;
    bool warp_geo = false;

    if (isD) {
        float lam = 0.001f * fmaxf(p[0], 0.0f);
        nlam = -lam;
        beta = fmaf(10.0f, fmaxf(p[1], 0.0f), 1.0f);
        kd   = p[2];
        nkd  = -kd;
    } else {
        mu = p[3];
        kf = p[4];
        float a = LOG2E_F / p[6];      // sigmoid: g = 1/(1 + 2^((nc-n)*a))
        z0 = p[5] * a;
        na = -a;
        c  = ex2a(na);                 // geometric ratio 2^{-a}
        warp_geo = __all_sync(0xffffffffu, fabsf(a) < 126.0f);
    }

    float* spd = &smd[li * SR];
    float* spf = &smf[li * SR];

    #pragma unroll 1
    for (int chunk = 0; chunk < 7; ++chunk) {
        int n0 = chunk * 32;
        int nsteps = (chunk < 6) ? 32 : 8;         // 200 = 6*32 + 8

        if (isD) {
            #pragma unroll 8
            for (int j = 0; j < nsteps; ++j) {
                float l  = lg2a(u);
                float pw = ex2a(beta * l);         // u^beta
                u = fmaf(nlam, pw, u);
                spd[j] = fmaf(nkd, u, kd);         // kd*D = kd*(1-u)
            }
        } else {
            #pragma unroll 1
            for (int g8 = 0; g8 < nsteps; g8 += 8) {
                float zs = fmaf((float)(n0 + g8), na, z0);   // exact group z
                float ze = fmaf(8.0f, na, zs);
                // hazard: e pinned at reseed (inf/FTZ-0) while true g crosses
                // back within the group (z monotone -> predicate exact)
                bool pin_cross = (zs >  126.0f && ze <  26.0f) ||
                                 (zs < -126.0f && ze > -26.0f);
                bool cheap = warp_geo && !__any_sync(0xffffffffu, pin_cross);
                if (cheap) {
                    float e = ex2a(zs);                      // exact reseed
                    #pragma unroll
                    for (int jj = 0; jj < 8; ++jj) {
                        float g = rcpa(1.0f + e);
                        e *= c;
                        float q = fmaf(mu, F, 1e-12f);
                        F = fminf(fmaxf(fmaf(g, q, F), 0.0f), 1.0f);
                        spf[g8 + jj] = kf * F;
                    }
                } else {
                    #pragma unroll
                    for (int jj = 0; jj < 8; ++jj) {
                        float z = fmaf((float)jj, na, zs);
                        float e = ex2a(z);                   // saturates safely
                        float g = rcpa(1.0f + e);
                        float q = fmaf(mu, F, 1e-12f);
                        F = fminf(fmaxf(fmaf(g, q, F), 0.0f), 1.0f);
                        spf[g8 + jj] = kf * F;
                    }
                }
            }
        }
        __syncthreads();
        // flush: kd*D + kf*F, coalesced float4 stores.
        if (nsteps == 32) {
            // 64 rows x 32 cols = 512 float4, 4 per thread.
            // q4 = it*128 + t: threads 0-7 share row, c = (q4&7)*4 -> warp
            // covers 4 rows = 4 full 128B lines; LDS banks (r+c)%32 distinct.
            #pragma unroll
            for (int it = 0; it < 4; ++it) {
                int q4 = it * BT + t;
                int r  = q4 >> 3;
                int cc = (q4 & 7) * 4;
                int sb = r * SR + cc;
                float4 v;
                v.x = smd[sb]     + smf[sb];
                v.y = smd[sb + 1] + smf[sb + 1];
                v.z = smd[sb + 2] + smf[sb + 2];
                v.w = smd[sb + 3] + smf[sb + 3];
                *reinterpret_cast<float4*>(
                    &out[(size_t)(base_lane + r) * 200 + n0 + cc]) = v;
            }
        } else {
            // 64 rows x 8 cols = 128 float4, 1 per thread.
            int r  = t >> 1;
            int cc = (t & 1) * 4;
            int sb = r * SR + cc;
            float4 v;
            v.x = smd[sb]     + smf[sb];
            v.y = smd[sb + 1] + smf[sb + 1];
            v.z = smd[sb + 2] + smf[sb + 2];
            v.w = smd[sb + 3] + smf[sb + 3];
            *reinterpret_cast<float4*>(
                &out[(size_t)(base_lane + r) * 200 + n0 + cc]) = v;
        }
        __syncthreads();
    }
}

// generic fallback for unexpected shapes
__global__ void __launch_bounds__(256) ist_generic(
    const float* __restrict__ in, float* __restrict__ out, int n_lanes)
{
    int tid = blockIdx.x * blockDim.x + threadIdx.x;
    if (tid >= n_lanes) return;
    const float* p = in + (size_t)tid * 7;
    float lam  = 0.001f * fmaxf(p[0], 0.0f);
    float beta = fmaf(10.0f, fmaxf(p[1], 0.0f), 1.0f);
    float kd = p[2], mu = p[3], kf = p[4];
    float a = LOG2E_F / p[6], z0 = p[5] * a;
    float u = 1.0f, F = 1e-12f, nf = 0.0f;
    float* o = out + (size_t)tid * 200;
    for (int n = 0; n < 200; ++n) {
        float l  = lg2a(fmaxf(u, 1e-12f));
        float pw = ex2a(beta * l);
        u = fminf(fmaxf(fmaf(-lam, pw, u), 0.0f), 1.0f);
        float z = fmaf(-nf, a, z0);
        float g = rcpa(1.0f + ex2a(z));
        float q = fmaf(mu, F, 1e-12f);
        F = fminf(fmaxf(fmaf(g, q, F), 0.0f), 1.0f);
        o[n] = fmaf(kf, F, fmaf(-kd, u, kd));
        nf += 1.0f;
    }
}

extern "C" void kernel_launch(void* const* d_in, const int* in_sizes, int n_in,
                              void* d_out, int out_size)
{
    const float* in = (const float*)d_in[0];
    float* out = (float*)d_out;
    int n_lanes = in_sizes[0] / 7;
    if (n_lanes % LPB == 0) {
        ist_split_kernel<<<n_lanes / LPB, BT>>>(in, out);
    } else {
        ist_generic<<<(n_lanes + 255) / 256, 256>>>(in, out, n_lanes);
    }
}

// round 12
// speedup vs baseline: 1.1672x; 1.0878x over previous
#include <cuda_runtime.h>

// ISTSimulator: B=65536, V=2, L=200 per-lane recurrence.
// Round 12: D-recurrence moved off MUFU. Track d = lam*u^beta and r ~= 1/u:
//   x=d*r; corr=1-bx+c2*x^2; d*=corr; u-=d; r*=(2-u*r)   (fma pipe, 0 MUFU)
// with exact MUFU reseed (lg2,ex2,rcp) every 8 steps. Warp-uniform vote
// beta*lam<0.05 gates it (else exact R9 path). F side: R9 geometric sigmoid
// with 8-step reseed + hazard votes. 128-thr blocks, 32-step smem staging.

#define LOG2E_F 1.4426950408889634f
#define SW 33                          // smem row stride (odd -> conflict-free)
#define BT 128                         // threads per block

__device__ __forceinline__ float ex2a(float x) {
    float r; asm("ex2.approx.ftz.f32 %0, %1;" : "=f"(r) : "f"(x)); return r;
}
__device__ __forceinline__ float lg2a(float x) {
    float r; asm("lg2.approx.f32 %0, %1;" : "=f"(r) : "f"(x)); return r;
}
__device__ __forceinline__ float rcpa(float x) {
    float r; asm("rcp.approx.ftz.f32 %0, %1;" : "=f"(r) : "f"(x)); return r;
}

__global__ void __launch_bounds__(BT) ist_taylor_kernel(
    const float* __restrict__ in, float* __restrict__ out)
{
    __shared__ float sm[BT * SW];      // 16.9 KB
    int t = threadIdx.x;
    int base_lane = blockIdx.x * BT;
    int lane = base_lane + t;

    const float* p = in + (size_t)lane * 7;
    float lam  = 0.001f * fmaxf(p[0], 0.0f);
    float beta = fmaf(10.0f, fmaxf(p[1], 0.0f), 1.0f);
    float kd   = p[2];
    float mu   = p[3];
    float kf   = p[4];
    float a    = LOG2E_F / p[6];       // sigmoid: g = 1/(1 + 2^((nc-n)*a))
    float z0   = p[5] * a;
    float na   = -a;
    float nkd  = -kd;
    float nlam = -lam;
    float c    = ex2a(na);             // geometric ratio 2^{-a}
    float nbeta = -beta;
    float c2   = 0.5f * beta * (beta - 1.0f);   // Taylor 2nd-order coeff

    // Warp-uniform gates (NaN params compare false -> exact path)
    bool warp_geo = __all_sync(0xffffffffu, fabsf(a) < 126.0f);
    bool d_cheap  = __all_sync(0xffffffffu, beta * lam < 0.05f);

    float u  = 1.0f;                   // u = 1 - D; stays in (0.38, 1]
    float F  = 1e-12f;
    float* sp = &sm[t * SW];

    #pragma unroll 1
    for (int chunk = 0; chunk < 7; ++chunk) {
        int n0 = chunk * 32;
        int nsteps = (chunk < 6) ? 32 : 8;         // 200 = 6*32 + 8

        #pragma unroll 1
        for (int g8 = 0; g8 < nsteps; g8 += 8) {
            float zs = fmaf((float)(n0 + g8), na, z0);   // exact group z
            float ze = fmaf(8.0f, na, zs);
            // F hazard: e pinned at reseed (inf/FTZ-0) while true g crosses
            // back within the group (z monotone -> predicate exact)
            bool pin_cross = (zs >  126.0f && ze <  26.0f) ||
                             (zs < -126.0f && ze > -26.0f);
            bool f_cheap = warp_geo && !__any_sync(0xffffffffu, pin_cross);

            if (d_cheap) {
                // exact D reseed: d = lam*u^beta, r ~= 1/u
                float l  = lg2a(u);
                float pw = ex2a(beta * l);
                float d  = lam * pw;
                float r  = rcpa(u);
                if (f_cheap) {
                    float e = ex2a(zs);
                    #pragma unroll
                    for (int jj = 0; jj < 8; ++jj) {
                        float g = rcpa(1.0f + e);
                        e *= c;
                        float q = fmaf(mu, F, 1e-12f);
                        F = fminf(fmaxf(fmaf(g, q, F), 0.0f), 1.0f);
                        float x  = d * r;
                        u = u - d;
                        float tt = fmaf(c2, x, nbeta);
                        d = d * fmaf(tt, x, 1.0f);
                        float a1 = fmaf(u, r, -2.0f);
                        r = -r * a1;                     // Newton: r*(2-u*r)
                        sp[g8 + jj] = fmaf(kf, F, fmaf(nkd, u, kd));
                    }
                } else {
                    #pragma unroll
                    for (int jj = 0; jj < 8; ++jj) {
                        float z = fmaf((float)jj, na, zs);
                        float e = ex2a(z);               // saturates safely
                        float g = rcpa(1.0f + e);
                        float q = fmaf(mu, F, 1e-12f);
                        F = fminf(fmaxf(fmaf(g, q, F), 0.0f), 1.0f);
                        float x  = d * r;
                        u = u - d;
                        float tt = fmaf(c2, x, nbeta);
                        d = d * fmaf(tt, x, 1.0f);
                        float a1 = fmaf(u, r, -2.0f);
                        r = -r * a1;
                        sp[g8 + jj] = fmaf(kf, F, fmaf(nkd, u, kd));
                    }
                }
            } else {
                // exact D path (R9)
                if (f_cheap) {
                    float e = ex2a(zs);
                    #pragma unroll
                    for (int jj = 0; jj < 8; ++jj) {
                        float l  = lg2a(u);
                        float pw = ex2a(beta * l);
                        u = fmaf(nlam, pw, u);
                        float g = rcpa(1.0f + e);
                        e *= c;
                        float q = fmaf(mu, F, 1e-12f);
                        F = fminf(fmaxf(fmaf(g, q, F), 0.0f), 1.0f);
                        sp[g8 + jj] = fmaf(kf, F, fmaf(nkd, u, kd));
                    }
                } else {
                    #pragma unroll
                    for (int jj = 0; jj < 8; ++jj) {
                        float l  = lg2a(u);
                        float pw = ex2a(beta * l);
                        u = fmaf(nlam, pw, u);
                        float z = fmaf((float)jj, na, zs);
                        float e = ex2a(z);
                        float g = rcpa(1.0f + e);
                        float q = fmaf(mu, F, 1e-12f);
                        F = fminf(fmaxf(fmaf(g, q, F), 0.0f), 1.0f);
                        sp[g8 + jj] = fmaf(kf, F, fmaf(nkd, u, kd));
                    }
                }
            }
        }
        __syncthreads();
        // coalesced flush (R9-proven): BT lanes x nsteps, float4 per thread
        if (nsteps == 32) {
            #pragma unroll
            for (int it = 0; it < 8; ++it) {
                int q4 = it * (BT * 4) + t * 4;
                int r  = q4 >> 5;
                int cc = q4 & 31;
                int sb = r * SW + cc;
                float4 v;
                v.x = sm[sb];
                v.y = sm[sb + 1];
                v.z = sm[sb + 2];
                v.w = sm[sb + 3];
                *reinterpret_cast<float4*>(
                    &out[(size_t)(base_lane + r) * 200 + n0 + cc]) = v;
            }
        } else {
            #pragma unroll
            for (int it = 0; it < 2; ++it) {
                int q4 = it * (BT * 4) + t * 4;
                int r  = q4 >> 3;
                int cc = q4 & 7;
                int sb = r * SW + cc;
                float4 v;
                v.x = sm[sb];
                v.y = sm[sb + 1];
                v.z = sm[sb + 2];
                v.w = sm[sb + 3];
                *reinterpret_cast<float4*>(
                    &out[(size_t)(base_lane + r) * 200 + n0 + cc]) = v;
            }
        }
        __syncthreads();
    }
}

// generic fallback for unexpected shapes
__global__ void __launch_bounds__(256) ist_generic(
    const float* __restrict__ in, float* __restrict__ out, int n_lanes)
{
    int tid = blockIdx.x * blockDim.x + threadIdx.x;
    if (tid >= n_lanes) return;
    const float* p = in + (size_t)tid * 7;
    float lam  = 0.001f * fmaxf(p[0], 0.0f);
    float beta = fmaf(10.0f, fmaxf(p[1], 0.0f), 1.0f);
    float kd = p[2], mu = p[3], kf = p[4];
    float a = LOG2E_F / p[6], z0 = p[5] * a;
    float u = 1.0f, F = 1e-12f, nf = 0.0f;
    float* o = out + (size_t)tid * 200;
    for (int n = 0; n < 200; ++n) {
        float l  = lg2a(fmaxf(u, 1e-12f));
        float pw = ex2a(beta * l);
        u = fminf(fmaxf(fmaf(-lam, pw, u), 0.0f), 1.0f);
        float z = fmaf(-nf, a, z0);
        float g = rcpa(1.0f + ex2a(z));
        float q = fmaf(mu, F, 1e-12f);
        F = fminf(fmaxf(fmaf(g, q, F), 0.0f), 1.0f);
        o[n] = fmaf(kf, F, fmaf(-kd, u, kd));
        nf += 1.0f;
    }
}

extern "C" void kernel_launch(void* const* d_in, const int* in_sizes, int n_in,
                              void* d_out, int out_size)
{
    const float* in = (const float*)d_in[0];
    float* out = (float*)d_out;
    int n_lanes = in_sizes[0] / 7;
    if (n_lanes % BT == 0) {
        ist_taylor_kernel<<<n_lanes / BT, BT>>>(in, out);
    } else {
        ist_generic<<<(n_lanes + 255) / 256, 256>>>(in, out, n_lanes);
    }
}

// round 13
// speedup vs baseline: 1.2379x; 1.0606x over previous
#include <cuda_runtime.h>

// ISTSimulator: B=65536, V=2, L=200 per-lane recurrence.
// Round 13: R12 + FFMA.SAT for the F clamp (2 instr + 8 chain-cycles/step) and
// 16-step reseed groups (half the reseed/vote overhead). Structure otherwise
// identical: Taylor-propagated D (fma pipe) + geometric sigmoid F, both with
// exact MUFU reseeds and warp-uniform hazard votes; 32-step smem staging.

#define LOG2E_F 1.4426950408889634f
#define SW 33                          // smem row stride (odd -> conflict-free)
#define BT 128                         // threads per block

__device__ __forceinline__ float ex2a(float x) {
    float r; asm("ex2.approx.ftz.f32 %0, %1;" : "=f"(r) : "f"(x)); return r;
}
__device__ __forceinline__ float lg2a(float x) {
    float r; asm("lg2.approx.f32 %0, %1;" : "=f"(r) : "f"(x)); return r;
}
__device__ __forceinline__ float rcpa(float x) {
    float r; asm("rcp.approx.ftz.f32 %0, %1;" : "=f"(r) : "f"(x)); return r;
}

struct LaneState {
    float u, F;                        // carried state
    float lam, nlam, beta, nbeta, c2;  // D params
    float kd, nkd, kf, mu;             // output / F params
    float na, z0, c;                   // sigmoid params
    bool d_cheap, warp_geo;
};

// Process LEN steps starting at absolute step n0g; stage into sp[ofs..].
template <int LEN>
__device__ __forceinline__ void do_group(LaneState& s, float* sp, int ofs, int n0g)
{
    float zs = fmaf((float)n0g, s.na, s.z0);         // exact group-start z
    float ze = fmaf((float)LEN, s.na, zs);           // group-end z
    // e pinned at reseed (inf/FTZ-0) while true g crosses back (z monotone)
    bool pin_cross = (zs >  126.0f && ze <  26.0f) ||
                     (zs < -126.0f && ze > -26.0f);
    bool f_cheap = s.warp_geo && !__any_sync(0xffffffffu, pin_cross);

    if (s.d_cheap) {
        // exact reseed: d = lam*u^beta, r ~= 1/u (MUFU, amortized /LEN)
        float l  = lg2a(s.u);
        float pw = ex2a(s.beta * l);
        float d  = s.lam * pw;
        float r  = rcpa(s.u);
        if (f_cheap) {
            float e = ex2a(zs);
            #pragma unroll
            for (int jj = 0; jj < LEN; ++jj) {
                float g = rcpa(1.0f + e);
                e *= s.c;
                float q = fmaf(s.mu, s.F, 1e-12f);
                s.F = __saturatef(fmaf(g, q, s.F));  // FFMA.SAT
                float x  = d * r;
                s.u = s.u - d;
                float tt = fmaf(s.c2, x, s.nbeta);
                d = d * fmaf(tt, x, 1.0f);
                float a1 = fmaf(s.u, r, -2.0f);
                r = -r * a1;                         // Newton: r*(2-u*r)
                sp[ofs + jj] = fmaf(s.kf, s.F, fmaf(s.nkd, s.u, s.kd));
            }
        } else {
            #pragma unroll
            for (int jj = 0; jj < LEN; ++jj) {
                float z = fmaf((float)jj, s.na, zs);
                float e = ex2a(z);                   // saturates safely
                float g = rcpa(1.0f + e);
                float q = fmaf(s.mu, s.F, 1e-12f);
                s.F = __saturatef(fmaf(g, q, s.F));
                float x  = d * r;
                s.u = s.u - d;
                float tt = fmaf(s.c2, x, s.nbeta);
                d = d * fmaf(tt, x, 1.0f);
                float a1 = fmaf(s.u, r, -2.0f);
                r = -r * a1;
                sp[ofs + jj] = fmaf(s.kf, s.F, fmaf(s.nkd, s.u, s.kd));
            }
        }
    } else {
        // exact D path (lg2+ex2 per step)
        if (f_cheap) {
            float e = ex2a(zs);
            #pragma unroll
            for (int jj = 0; jj < LEN; ++jj) {
                float l  = lg2a(s.u);
                float pw = ex2a(s.beta * l);
                s.u = fmaf(s.nlam, pw, s.u);
                float g = rcpa(1.0f + e);
                e *= s.c;
                float q = fmaf(s.mu, s.F, 1e-12f);
                s.F = __saturatef(fmaf(g, q, s.F));
                sp[ofs + jj] = fmaf(s.kf, s.F, fmaf(s.nkd, s.u, s.kd));
            }
        } else {
            #pragma unroll
            for (int jj = 0; jj < LEN; ++jj) {
                float l  = lg2a(s.u);
                float pw = ex2a(s.beta * l);
                s.u = fmaf(s.nlam, pw, s.u);
                float z = fmaf((float)jj, s.na, zs);
                float e = ex2a(z);
                float g = rcpa(1.0f + e);
                float q = fmaf(s.mu, s.F, 1e-12f);
                s.F = __saturatef(fmaf(g, q, s.F));
                sp[ofs + jj] = fmaf(s.kf, s.F, fmaf(s.nkd, s.u, s.kd));
            }
        }
    }
}

__global__ void __launch_bounds__(BT) ist_kernel(
    const float* __restrict__ in, float* __restrict__ out)
{
    __shared__ float sm[BT * SW];      // 16.9 KB
    int t = threadIdx.x;
    int base_lane = blockIdx.x * BT;
    int lane = base_lane + t;

    const float* p = in + (size_t)lane * 7;
    LaneState s;
    s.lam  = 0.001f * fmaxf(p[0], 0.0f);
    s.nlam = -s.lam;
    s.beta = fmaf(10.0f, fmaxf(p[1], 0.0f), 1.0f);
    s.nbeta = -s.beta;
    s.c2   = 0.5f * s.beta * (s.beta - 1.0f);
    s.kd   = p[2];
    s.nkd  = -s.kd;
    s.mu   = p[3];
    s.kf   = p[4];
    float a = LOG2E_F / p[6];
    s.z0  = p[5] * a;
    s.na  = -a;
    s.c   = ex2a(s.na);
    s.warp_geo = __all_sync(0xffffffffu, fabsf(a) < 126.0f);
    s.d_cheap  = __all_sync(0xffffffffu, s.beta * s.lam < 0.05f);
    s.u = 1.0f;                        // u = 1 - D; stays in (0.38, 1]
    s.F = 1e-12f;

    float* sp = &sm[t * SW];

    #pragma unroll 1
    for (int chunk = 0; chunk < 7; ++chunk) {
        int n0 = chunk * 32;
        bool full = (chunk < 6);       // 200 = 6*32 + 8

        if (full) {
            do_group<16>(s, sp, 0,  n0);
            do_group<16>(s, sp, 16, n0 + 16);
        } else {
            do_group<8>(s, sp, 0, n0);
        }
        __syncthreads();
        // coalesced flush: BT lanes x nsteps, float4 per thread
        if (full) {
            #pragma unroll
            for (int it = 0; it < 8; ++it) {
                int q4 = it * (BT * 4) + t * 4;
                int r  = q4 >> 5;
                int cc = q4 & 31;
                int sb = r * SW + cc;
                float4 v;
                v.x = sm[sb];
                v.y = sm[sb + 1];
                v.z = sm[sb + 2];
                v.w = sm[sb + 3];
                *reinterpret_cast<float4*>(
                    &out[(size_t)(base_lane + r) * 200 + n0 + cc]) = v;
            }
        } else {
            #pragma unroll
            for (int it = 0; it < 2; ++it) {
                int q4 = it * (BT * 4) + t * 4;
                int r  = q4 >> 3;
                int cc = q4 & 7;
                int sb = r * SW + cc;
                float4 v;
                v.x = sm[sb];
                v.y = sm[sb + 1];
                v.z = sm[sb + 2];
                v.w = sm[sb + 3];
                *reinterpret_cast<float4*>(
                    &out[(size_t)(base_lane + r) * 200 + n0 + cc]) = v;
            }
        }
        __syncthreads();
    }
}

// generic fallback for unexpected shapes
__global__ void __launch_bounds__(256) ist_generic(
    const float* __restrict__ in, float* __restrict__ out, int n_lanes)
{
    int tid = blockIdx.x * blockDim.x + threadIdx.x;
    if (tid >= n_lanes) return;
    const float* p = in + (size_t)tid * 7;
    float lam  = 0.001f * fmaxf(p[0], 0.0f);
    float beta = fmaf(10.0f, fmaxf(p[1], 0.0f), 1.0f);
    float kd = p[2], mu = p[3], kf = p[4];
    float a = LOG2E_F / p[6], z0 = p[5] * a;
    float u = 1.0f, F = 1e-12f, nf = 0.0f;
    float* o = out + (size_t)tid * 200;
    for (int n = 0; n < 200; ++n) {
        float l  = lg2a(fmaxf(u, 1e-12f));
        float pw = ex2a(beta * l);
        u = fminf(fmaxf(fmaf(-lam, pw, u), 0.0f), 1.0f);
        float z = fmaf(-nf, a, z0);
        float g = rcpa(1.0f + ex2a(z));
        float q = fmaf(mu, F, 1e-12f);
        F = __saturatef(fmaf(g, q, F));
        o[n] = fmaf(kf, F, fmaf(-kd, u, kd));
        nf += 1.0f;
    }
}

extern "C" void kernel_launch(void* const* d_in, const int* in_sizes, int n_in,
                              void* d_out, int out_size)
{
    const float* in = (const float*)d_in[0];
    float* out = (float*)d_out;
    int n_lanes = in_sizes[0] / 7;
    if (n_lanes % BT == 0) {
        ist_kernel<<<n_lanes / BT, BT>>>(in, out);
    } else {
        ist_generic<<<(n_lanes + 255) / 256, 256>>>(in, out, n_lanes);
    }
}